// round 14
// baseline (speedup 1.0000x reference)
#include <cuda_runtime.h>
#include <cuda_bf16.h>
#include <math.h>
#include <float.h>
#include <stdint.h>

// Problem constants (fixed shapes)
#define NN   64000      // nodes
#define NPGc 500        // nodes per graph
#define GG   128        // graphs
#define EE   131072     // edges
#define DIN  768        // input dim
#define HH   512        // hidden
#define CC   4          // classes
#define KKc  250        // kept nodes per graph
#define EPSc 1e-5f

// split-GEMM: 12 chunks of K=64; 3 products (Ah*Bh, Al*Bh, Ah*Bl)
#define KSPLIT   1536   // row stride of W-split buffer (hi 768 | lo 768)
#define NSUPER   12

// ---------------- scratch (static device globals; no allocation) -------------
__device__ float d_dinv[NN];
__device__ int   d_cnt[NN];          // zero-init; re-zeroed by gather each run
__device__ int   d_rowptr[NN + 1];
__device__ int   d_cur[NN];
__device__ int   d_esrc[EE];
__device__ float d_h0[NN * HH];
__device__ float d_h [NN * HH];
__device__ float d_s2[NN];
__device__ float d_s [NN];
__device__ float d_S  [GG * HH];
__device__ float d_ssq[HH];          // zero-init; re-zeroed by final each run
__device__ __nv_bfloat16 d_ws[(size_t)HH * KSPLIT];   // W^T split: [n][hi 768 | lo 768]

__device__ __forceinline__ uint32_t smem_u32(const void* p) {
    uint32_t a;
    asm("{ .reg .u64 t; cvta.to.shared.u64 t, %1; cvt.u32.u64 %0, t; }" : "=r"(a) : "l"(p));
    return a;
}

__device__ __forceinline__ void cp_async16(uint32_t dst, const void* src) {
    asm volatile("cp.async.cg.shared.global [%0], [%1], 16;" :: "r"(dst), "l"(src));
}

// pack two floats as bf16x2: first arg -> low half, second -> high half
__device__ __forceinline__ uint32_t pack_bf16(float lo, float hi) {
    uint32_t r;
    asm("cvt.rn.bf16x2.f32 %0, %1, %2;" : "=r"(r) : "f"(hi), "f"(lo));
    return r;
}

// ---------------- fused: W split conversion + CSR degree count ---------------
__global__ void prep_kernel(const float* __restrict__ w, const int* __restrict__ dst) {
    int i = blockIdx.x * blockDim.x + threadIdx.x;
    if (i < DIN * HH) {
        int k = i / HH, n = i - k * HH;
        float v = w[i];
        __nv_bfloat16 hi = __float2bfloat16(v);
        __nv_bfloat16 lo = __float2bfloat16(v - __bfloat162float(hi));
        d_ws[(size_t)n * KSPLIT + k] = hi;
        d_ws[(size_t)n * KSPLIT + DIN + k] = lo;
    }
    if (i < EE) atomicAdd(&d_cnt[dst[i]], 1);
}

__global__ __launch_bounds__(1024) void csr_scan_kernel() {
    __shared__ int wsum[32];
    __shared__ int chunk_total;
    int tid = threadIdx.x;
    int lane = tid & 31, w = tid >> 5;
    int running = 0;
    for (int base = 0; base < NN; base += 1024) {
        int i = base + tid;
        int v = (i < NN) ? d_cnt[i] : 0;
        int incl = v;
        #pragma unroll
        for (int o = 1; o < 32; o <<= 1) {
            int t = __shfl_up_sync(0xffffffffu, incl, o);
            if (lane >= o) incl += t;
        }
        if (lane == 31) wsum[w] = incl;
        __syncthreads();
        if (w == 0) {
            int s = wsum[lane];
            #pragma unroll
            for (int o = 1; o < 32; o <<= 1) {
                int t = __shfl_up_sync(0xffffffffu, s, o);
                if (lane >= o) s += t;
            }
            wsum[lane] = s;
            if (lane == 31) chunk_total = s;
        }
        __syncthreads();
        int excl = running + (w > 0 ? wsum[w - 1] : 0) + incl - v;
        if (i < NN) {
            d_rowptr[i] = excl;
            d_cur[i]    = excl;
            d_dinv[i]   = rsqrtf(1.0f + (float)v);   // self-loop degree
        }
        running += chunk_total;
        __syncthreads();
    }
    if (tid == 0) d_rowptr[NN] = EE;
}

__global__ void csr_fill_kernel(const int* __restrict__ src, const int* __restrict__ dst) {
    int e = blockIdx.x * blockDim.x + threadIdx.x;
    if (e < EE) {
        int pos = atomicAdd(&d_cur[dst[e]], 1);
        d_esrc[pos] = src[e];
    }
}

// ---------------- HMMA GEMM: h0 = x @ W  (bf16 split, in-kernel A split) ----
// CTA tile 128(M) x 256(N). SMEM: fp32 A staging 32KB; 2 x {AHI 16K, ALO 16K};
// 2 x {BHI 32K, BLO 32K}. 8 warps: 2(M) x 4(N), warp tile 64x64.  (R9 form)
#define STG_OFF   0
#define A_OFF     32768     // + buf*32768 ; ALO = +16384
#define B_OFF     98304     // + buf*65536 ; BLO = +32768
#define SMEM_TOTAL_GEMM 229376

__device__ __forceinline__ void load_A_fp32(uint32_t sb, const float* x, int sc, int m0) {
    int tid = threadIdx.x;
    #pragma unroll
    for (int i = 0; i < 8; i++) {               // 128 rows x 16 16B-chunks
        int idx = tid + i * 256;
        int r = idx >> 4, u = idx & 15;
        cp_async16(sb + STG_OFF + r * 256 + u * 16,
                   x + (size_t)(m0 + r) * DIN + sc * 64 + u * 4);
    }
}

__device__ __forceinline__ void load_B(uint32_t sb, int buf, int sc, int n0) {
    uint32_t base = sb + B_OFF + buf * 65536;
    int tid = threadIdx.x;
    #pragma unroll
    for (int i = 0; i < 8; i++) {               // 256 rows x 8 chunks
        int idx = tid + i * 256;
        int r = idx >> 3, t = idx & 7;
        uint32_t sw = (uint32_t)(r * 128 + ((t ^ (r & 7)) << 4));
        const __nv_bfloat16* brow = d_ws + (size_t)(n0 + r) * KSPLIT + sc * 64 + t * 8;
        cp_async16(base + sw, brow);
        cp_async16(base + 32768 + sw, brow + DIN);
    }
}

// split staging fp32 -> AHI/ALO bf16 (swizzled)
__device__ __forceinline__ void convert_A(char* smem, int buf) {
    int tid = threadIdx.x;
    char* stg = smem + STG_OFF;
    char* ahi = smem + A_OFF + buf * 32768;
    char* alo = ahi + 16384;
    #pragma unroll
    for (int i = 0; i < 4; i++) {               // 128 rows x 8 t-units
        int unit = tid + i * 256;
        int r = unit >> 3, t = unit & 7;
        const float4* s = (const float4*)(stg + r * 256 + t * 32);
        float4 v0 = s[0], v1 = s[1];
        float h0 = __bfloat162float(__float2bfloat16(v0.x));
        float h1 = __bfloat162float(__float2bfloat16(v0.y));
        float h2 = __bfloat162float(__float2bfloat16(v0.z));
        float h3 = __bfloat162float(__float2bfloat16(v0.w));
        float h4 = __bfloat162float(__float2bfloat16(v1.x));
        float h5 = __bfloat162float(__float2bfloat16(v1.y));
        float h6 = __bfloat162float(__float2bfloat16(v1.z));
        float h7 = __bfloat162float(__float2bfloat16(v1.w));
        uint4 hv, lv;
        hv.x = pack_bf16(h0, h1);  hv.y = pack_bf16(h2, h3);
        hv.z = pack_bf16(h4, h5);  hv.w = pack_bf16(h6, h7);
        lv.x = pack_bf16(v0.x - h0, v0.y - h1);
        lv.y = pack_bf16(v0.z - h2, v0.w - h3);
        lv.z = pack_bf16(v1.x - h4, v1.y - h5);
        lv.w = pack_bf16(v1.z - h6, v1.w - h7);
        uint32_t sw = (uint32_t)(r * 128 + ((t ^ (r & 7)) << 4));
        *(uint4*)(ahi + sw) = hv;
        *(uint4*)(alo + sw) = lv;
    }
}

__device__ __forceinline__ void ldmx4(uint32_t& r0, uint32_t& r1, uint32_t& r2,
                                      uint32_t& r3, uint32_t addr) {
    asm volatile("ldmatrix.sync.aligned.m8n8.x4.shared.b16 {%0,%1,%2,%3}, [%4];"
                 : "=r"(r0), "=r"(r1), "=r"(r2), "=r"(r3) : "r"(addr));
}

__device__ __forceinline__ void mma16816(float* c, const uint32_t* a, const uint32_t* b) {
    asm volatile(
        "mma.sync.aligned.m16n8k16.row.col.f32.bf16.bf16.f32 "
        "{%0,%1,%2,%3}, {%4,%5,%6,%7}, {%8,%9}, {%0,%1,%2,%3};"
        : "+f"(c[0]), "+f"(c[1]), "+f"(c[2]), "+f"(c[3])
        : "r"(a[0]), "r"(a[1]), "r"(a[2]), "r"(a[3]), "r"(b[0]), "r"(b[1]));
}

__global__ __launch_bounds__(256) void gemm_mma_kernel(const float* __restrict__ x) {
    extern __shared__ __align__(1024) char smem[];
    uint32_t sb = smem_u32(smem);
    const int tid  = threadIdx.x;
    const int wid  = tid >> 5, lane = tid & 31;
    const int n0 = blockIdx.x * 256;
    const int m0 = blockIdx.y * 128;
    const int wm = (wid & 1) * 64;        // warp M offset
    const int wn = (wid >> 1) * 64;       // warp N offset

    const int q  = lane >> 3;             // ldmatrix matrix index 0..3
    const int rq = lane & 7;
    const int a_rowl   = (q & 1) * 8 + rq;
    const int a_chunkq = q >> 1;
    const int b_rowl   = (q >> 1) * 8 + rq;
    const int b_chunkq = q & 1;

    float acc[4][8][4];
    #pragma unroll
    for (int i = 0; i < 4; i++)
        #pragma unroll
        for (int j = 0; j < 8; j++)
            #pragma unroll
            for (int v = 0; v < 4; v++) acc[i][j][v] = 0.f;

    // prologue: stage 0 loads
    load_A_fp32(sb, x, 0, m0);
    load_B(sb, 0, 0, n0);
    asm volatile("cp.async.commit_group;" ::: "memory");

    for (int sc = 0; sc < NSUPER; ++sc) {
        int buf = sc & 1;
        asm volatile("cp.async.wait_group 0;" ::: "memory");
        __syncthreads();                        // all warps past compute sc-1
        convert_A(smem, buf);
        __syncthreads();                        // staging free, A(buf) visible
        if (sc + 1 < NSUPER) {
            load_A_fp32(sb, x, sc + 1, m0);
            load_B(sb, (sc + 1) & 1, sc + 1, n0);
        }
        asm volatile("cp.async.commit_group;" ::: "memory");

        uint32_t Ahi = sb + A_OFF + buf * 32768;
        uint32_t Alo = Ahi + 16384;
        uint32_t Bhi = sb + B_OFF + buf * 65536;
        uint32_t Blo = Bhi + 32768;

        #pragma unroll
        for (int ks = 0; ks < 4; ++ks) {
            uint32_t ah[4][4], al[4][4];
            uint32_t b[8][2];
            // A-hi frags
            #pragma unroll
            for (int mi = 0; mi < 4; ++mi) {
                int row = wm + mi * 16 + a_rowl;
                uint32_t addr = Ahi + row * 128 +
                                (uint32_t)(((ks * 2 + a_chunkq) ^ (row & 7)) << 4);
                ldmx4(ah[mi][0], ah[mi][1], ah[mi][2], ah[mi][3], addr);
            }
            // B-hi frags
            #pragma unroll
            for (int nj = 0; nj < 4; ++nj) {
                int n = wn + nj * 16 + b_rowl;
                uint32_t addr = Bhi + n * 128 +
                                (uint32_t)(((ks * 2 + b_chunkq) ^ (n & 7)) << 4);
                uint32_t r0, r1, r2, r3;
                ldmx4(r0, r1, r2, r3, addr);
                b[nj * 2 + 0][0] = r0; b[nj * 2 + 0][1] = r1;
                b[nj * 2 + 1][0] = r2; b[nj * 2 + 1][1] = r3;
            }
            #pragma unroll
            for (int mi = 0; mi < 4; ++mi)
                #pragma unroll
                for (int nj = 0; nj < 8; ++nj)
                    mma16816(acc[mi][nj], ah[mi], b[nj]);
            // A-lo ; Al x Bh
            #pragma unroll
            for (int mi = 0; mi < 4; ++mi) {
                int row = wm + mi * 16 + a_rowl;
                uint32_t addr = Alo + row * 128 +
                                (uint32_t)(((ks * 2 + a_chunkq) ^ (row & 7)) << 4);
                ldmx4(al[mi][0], al[mi][1], al[mi][2], al[mi][3], addr);
            }
            #pragma unroll
            for (int mi = 0; mi < 4; ++mi)
                #pragma unroll
                for (int nj = 0; nj < 8; ++nj)
                    mma16816(acc[mi][nj], al[mi], b[nj]);
            // B-lo ; Ah x Bl
            #pragma unroll
            for (int nj = 0; nj < 4; ++nj) {
                int n = wn + nj * 16 + b_rowl;
                uint32_t addr = Blo + n * 128 +
                                (uint32_t)(((ks * 2 + b_chunkq) ^ (n & 7)) << 4);
                uint32_t r0, r1, r2, r3;
                ldmx4(r0, r1, r2, r3, addr);
                b[nj * 2 + 0][0] = r0; b[nj * 2 + 0][1] = r1;
                b[nj * 2 + 1][0] = r2; b[nj * 2 + 1][1] = r3;
            }
            #pragma unroll
            for (int mi = 0; mi < 4; ++mi)
                #pragma unroll
                for (int nj = 0; nj < 8; ++nj)
                    mma16816(acc[mi][nj], ah[mi], b[nj]);
        }
    }

    // epilogue
    const int erow = lane >> 2;
    const int ecol = (lane & 3) * 2;
    #pragma unroll
    for (int mi = 0; mi < 4; ++mi) {
        #pragma unroll
        for (int nj = 0; nj < 8; ++nj) {
            int gr = m0 + wm + mi * 16 + erow;
            int gc = n0 + wn + nj * 8 + ecol;
            float* o0 = &d_h0[(size_t)gr * HH + gc];
            o0[0] = acc[mi][nj][0];
            o0[1] = acc[mi][nj][1];
            float* o1 = &d_h0[(size_t)(gr + 8) * HH + gc];
            o1[0] = acc[mi][nj][2];
            o1[1] = acc[mi][nj][3];
        }
    }
}

// ---------------- fused gather: agg + self + bias + relu + score dots -------
// 2 nodes per 256-thread block: threads [0,128) -> node 2b, [128,256) -> 2b+1.
__global__ __launch_bounds__(256) void gather_kernel(
    const float* __restrict__ gcn_b, const float* __restrict__ w1,
    const float* __restrict__ w2,    const float* __restrict__ sag_b) {
    __shared__ float red[16];   // 8 warps x {a,b}
    int half = threadIdx.x >> 7;            // 0 or 1
    int n = blockIdx.x * 2 + half;
    int tid = threadIdx.x & 127;
    int lane = threadIdx.x & 31, w = threadIdx.x >> 5;
    int beg = d_rowptr[n], end = d_rowptr[n + 1];
    float din = d_dinv[n];
    int f = tid * 4;

    float4 hv = *(const float4*)&d_h0[(size_t)n * HH + f];
    float d2 = din * din;
    float4 acc = make_float4(hv.x * d2, hv.y * d2, hv.z * d2, hv.w * d2);

    for (int j = beg; j < end; ++j) {
        int s = d_esrc[j];
        float c = d_dinv[s] * din;
        float4 xv = *(const float4*)&d_h0[(size_t)s * HH + f];
        acc.x += xv.x * c;
        acc.y += xv.y * c;
        acc.z += xv.z * c;
        acc.w += xv.w * c;
    }
    float4 bv = *(const float4*)&gcn_b[f];
    acc.x = fmaxf(acc.x + bv.x, 0.f);
    acc.y = fmaxf(acc.y + bv.y, 0.f);
    acc.z = fmaxf(acc.z + bv.z, 0.f);
    acc.w = fmaxf(acc.w + bv.w, 0.f);
    *(float4*)&d_h[(size_t)n * HH + f] = acc;

    float4 w1v = *(const float4*)&w1[f];
    float4 w2v = *(const float4*)&w2[f];
    float a = acc.x * w1v.x + acc.y * w1v.y + acc.z * w1v.z + acc.w * w1v.w;
    float b = acc.x * w2v.x + acc.y * w2v.y + acc.z * w2v.z + acc.w * w2v.w;
    #pragma unroll
    for (int o = 16; o > 0; o >>= 1) {
        a += __shfl_down_sync(0xffffffffu, a, o);
        b += __shfl_down_sync(0xffffffffu, b, o);
    }
    if (lane == 0) { red[w] = a; red[w + 8] = b; }
    __syncthreads();
    if (tid == 0) {
        int base = half * 4;
        d_s[n]  = red[base] + red[base + 1] + red[base + 2] + red[base + 3] + sag_b[0];
        d_s2[n] = red[base + 8] + red[base + 9] + red[base + 10] + red[base + 11];
        d_cnt[n] = 0;      // self-clean for next invocation
    }
}

__global__ void score_edge_kernel(const int* __restrict__ src, const int* __restrict__ dst) {
    int e = blockIdx.x * blockDim.x + threadIdx.x;
    if (e < EE) atomicAdd(&d_s[dst[e]], d_s2[src[e]]);
}

// ---------------- fused topk(250 of 500) + pooled sums ----------------------
__global__ __launch_bounds__(256) void topk_pool_kernel() {
    __shared__ float key[512];
    __shared__ int   kid[512];
    __shared__ float st[KKc];
    int g = blockIdx.x;
    int tid = threadIdx.x;
    for (int i = tid; i < 512; i += 256) {
        if (i < NPGc) { key[i] = d_s[g * NPGc + i]; kid[i] = i; }
        else          { key[i] = -FLT_MAX;          kid[i] = i; }
    }
    for (int k = 2; k <= 512; k <<= 1) {
        for (int j = k >> 1; j > 0; j >>= 1) {
            __syncthreads();
            for (int t = tid; t < 512; t += 256) {
                int p = t ^ j;
                if (p > t) {
                    float ka = key[t], kb = key[p];
                    int   ia = kid[t], ib = kid[p];
                    bool b_gt_a = (kb > ka) || (kb == ka && ib < ia);
                    bool desc = ((t & k) == 0);
                    bool do_swap = desc ? b_gt_a : (!b_gt_a && (ka != kb || ia != ib));
                    if (do_swap) {
                        key[t] = kb; key[p] = ka;
                        kid[t] = ib; kid[p] = ia;
                    }
                }
            }
        }
    }
    __syncthreads();
    if (tid < KKc) st[tid] = tanhf(key[tid]);
    __syncthreads();

    int f1 = tid, f2 = tid + 256;
    float s1 = 0.f, q1 = 0.f, s2 = 0.f, q2 = 0.f;
    for (int k = 0; k < KKc; k++) {
        const float* hr = &d_h[(size_t)(g * NPGc + kid[k]) * HH];
        float t = st[k];
        float v1 = hr[f1] * t;
        float v2 = hr[f2] * t;
        s1 += v1; q1 += v1 * v1;
        s2 += v2; q2 += v2 * v2;
    }
    d_S[g * HH + f1] = s1;
    d_S[g * HH + f2] = s2;
    atomicAdd(&d_ssq[f1], q1);
    atomicAdd(&d_ssq[f2], q2);
}

// ---------------- BN (fused) + mean-pool + FC + log_softmax -----------------
__global__ __launch_bounds__(512) void final_kernel(
    const float* __restrict__ gamma, const float* __restrict__ beta,
    const float* __restrict__ fc_w,  const float* __restrict__ fc_b,
    float* __restrict__ out) {
    __shared__ float mu[HH], rstd[HH], lg[GG * CC];
    int tid = threadIdx.x;
    {
        int f = tid;
        float cs = 0.f;
        for (int g = 0; g < GG; g++) cs += d_S[g * HH + f];
        float m = cs * (1.0f / (GG * KKc));
        float ss = d_ssq[f];
        d_ssq[f] = 0.f;                    // self-clean for next invocation
        float var = ss * (1.0f / (GG * KKc)) - m * m;
        mu[f] = m;
        rstd[f] = rsqrtf(var + EPSc);
    }
    __syncthreads();
    {
        int g = tid >> 2, c = tid & 3;
        float acc = fc_b[c];
        for (int f = 0; f < HH; f++) {
            float pooled = (d_S[g * HH + f] * (1.0f / KKc) - mu[f]) * rstd[f] * gamma[f] + beta[f];
            acc += pooled * fc_w[f * CC + c];
        }
        lg[tid] = acc;
    }
    __syncthreads();
    if (tid < GG) {
        float l0 = lg[tid * 4 + 0], l1 = lg[tid * 4 + 1];
        float l2 = lg[tid * 4 + 2], l3 = lg[tid * 4 + 3];
        float m = fmaxf(fmaxf(l0, l1), fmaxf(l2, l3));
        float lse = m + logf(expf(l0 - m) + expf(l1 - m) + expf(l2 - m) + expf(l3 - m));
        out[tid * 4 + 0] = l0 - lse;
        out[tid * 4 + 1] = l1 - lse;
        out[tid * 4 + 2] = l2 - lse;
        out[tid * 4 + 3] = l3 - lse;
    }
}

// ---------------- launch ----------------
extern "C" void kernel_launch(void* const* d_in, const int* in_sizes, int n_in,
                              void* d_out, int out_size) {
    const float* x      = (const float*)d_in[0];
    const float* gcn_w  = (const float*)d_in[1];
    const float* gcn_b  = (const float*)d_in[2];
    const float* sag_w1 = (const float*)d_in[3];
    const float* sag_w2 = (const float*)d_in[4];
    const float* sag_b  = (const float*)d_in[5];
    const float* bn_g   = (const float*)d_in[6];
    const float* bn_b   = (const float*)d_in[7];
    const float* fc_w   = (const float*)d_in[8];
    const float* fc_b   = (const float*)d_in[9];
    const int*   ei     = (const int*)d_in[10];
    const int* src = ei;
    const int* dst = ei + EE;
    float* out = (float*)d_out;

    cudaFuncSetAttribute(gemm_mma_kernel, cudaFuncAttributeMaxDynamicSharedMemorySize,
                         SMEM_TOTAL_GEMM);

    // gemm kept as 4th launch (ncu capture lands there)
    prep_kernel<<<(DIN * HH) / 256, 256>>>(gcn_w, dst);
    csr_scan_kernel<<<1, 1024>>>();
    csr_fill_kernel<<<(EE + 255) / 256, 256>>>(src, dst);
    gemm_mma_kernel<<<dim3(HH / 256, NN / 128), 256, SMEM_TOTAL_GEMM>>>(x);
    gather_kernel<<<NN / 2, 256>>>(gcn_b, sag_w1, sag_w2, sag_b);
    score_edge_kernel<<<(EE + 255) / 256, 256>>>(src, dst);
    topk_pool_kernel<<<GG, 256>>>();
    final_kernel<<<1, 512>>>(bn_g, bn_b, fc_w, fc_b, out);
}

// round 17
// speedup vs baseline: 1.0146x; 1.0146x over previous
#include <cuda_runtime.h>
#include <cuda_bf16.h>
#include <math.h>
#include <float.h>
#include <stdint.h>

// Problem constants (fixed shapes)
#define NN   64000      // nodes
#define NPGc 500        // nodes per graph
#define GG   128        // graphs
#define EE   131072     // edges
#define DIN  768        // input dim
#define HH   512        // hidden
#define CC   4          // classes
#define KKc  250        // kept nodes per graph
#define EPSc 1e-5f

// split-GEMM: 12 chunks of K=64; 3 products (Ah*Bh, Al*Bh, Ah*Bl)
#define KSPLIT   1536   // row stride of W-split buffer (hi 768 | lo 768)
#define NSUPER   12

// ---------------- scratch (static device globals; no allocation) -------------
__device__ float d_dinv[NN];
__device__ int   d_cnt[NN];          // zero-init; re-zeroed by gather each run
__device__ int   d_rowptr[NN + 1];
__device__ int   d_cur[NN];
__device__ int   d_esrc[EE];
__device__ float d_h0[NN * HH];
__device__ float d_h [NN * HH];
__device__ float d_s2[NN];
__device__ float d_s [NN];
__device__ float d_S  [GG * HH];
__device__ float d_ssq[HH];          // zero-init; re-zeroed by final each run
__device__ __nv_bfloat16 d_ws[(size_t)HH * KSPLIT];   // W^T split: [n][hi 768 | lo 768]

__device__ __forceinline__ uint32_t smem_u32(const void* p) {
    uint32_t a;
    asm("{ .reg .u64 t; cvta.to.shared.u64 t, %1; cvt.u32.u64 %0, t; }" : "=r"(a) : "l"(p));
    return a;
}

__device__ __forceinline__ void cp_async16(uint32_t dst, const void* src) {
    asm volatile("cp.async.cg.shared.global [%0], [%1], 16;" :: "r"(dst), "l"(src));
}

// pack two floats as bf16x2: first arg -> low half, second -> high half
__device__ __forceinline__ uint32_t pack_bf16(float lo, float hi) {
    uint32_t r;
    asm("cvt.rn.bf16x2.f32 %0, %1, %2;" : "=r"(r) : "f"(hi), "f"(lo));
    return r;
}

// ---------------- CSR build ----------------
__global__ void csr_count_kernel(const int* __restrict__ dst) {
    int e = blockIdx.x * blockDim.x + threadIdx.x;
    if (e < EE) atomicAdd(&d_cnt[dst[e]], 1);
}

__global__ __launch_bounds__(1024) void csr_scan_kernel() {
    __shared__ int wsum[32];
    __shared__ int chunk_total;
    int tid = threadIdx.x;
    int lane = tid & 31, w = tid >> 5;
    int running = 0;
    for (int base = 0; base < NN; base += 1024) {
        int i = base + tid;
        int v = (i < NN) ? d_cnt[i] : 0;
        int incl = v;
        #pragma unroll
        for (int o = 1; o < 32; o <<= 1) {
            int t = __shfl_up_sync(0xffffffffu, incl, o);
            if (lane >= o) incl += t;
        }
        if (lane == 31) wsum[w] = incl;
        __syncthreads();
        if (w == 0) {
            int s = wsum[lane];
            #pragma unroll
            for (int o = 1; o < 32; o <<= 1) {
                int t = __shfl_up_sync(0xffffffffu, s, o);
                if (lane >= o) s += t;
            }
            wsum[lane] = s;
            if (lane == 31) chunk_total = s;
        }
        __syncthreads();
        int excl = running + (w > 0 ? wsum[w - 1] : 0) + incl - v;
        if (i < NN) {
            d_rowptr[i] = excl;
            d_cur[i]    = excl;
            d_dinv[i]   = rsqrtf(1.0f + (float)v);   // self-loop degree
        }
        running += chunk_total;
        __syncthreads();
    }
    if (tid == 0) d_rowptr[NN] = EE;
}

__global__ void csr_fill_kernel(const int* __restrict__ src, const int* __restrict__ dst) {
    int e = blockIdx.x * blockDim.x + threadIdx.x;
    if (e < EE) {
        int pos = atomicAdd(&d_cur[dst[e]], 1);
        d_esrc[pos] = src[e];
    }
}

// ---------------- W split conversion (x is split inside the GEMM) -----------
__global__ void convert_w_kernel(const float* __restrict__ w) {
    int i = blockIdx.x * blockDim.x + threadIdx.x;   // DIN*HH threads
    int k = i / HH, n = i - k * HH;
    float v = w[i];
    __nv_bfloat16 hi = __float2bfloat16(v);
    __nv_bfloat16 lo = __float2bfloat16(v - __bfloat162float(hi));
    d_ws[(size_t)n * KSPLIT + k] = hi;
    d_ws[(size_t)n * KSPLIT + DIN + k] = lo;
}

// ---------------- HMMA GEMM: h0 = x @ W  (bf16 split, in-kernel A split) ----
// CTA tile 128(M) x 256(N). SMEM: fp32 A staging 32KB; 2 x {AHI 16K, ALO 16K};
// 2 x {BHI 32K, BLO 32K}. 8 warps: 2(M) x 4(N), warp tile 64x64.
#define STG_OFF   0
#define A_OFF     32768     // + buf*32768 ; ALO = +16384
#define B_OFF     98304     // + buf*65536 ; BLO = +32768
#define SMEM_TOTAL_GEMM 229376

__device__ __forceinline__ void load_A_fp32(uint32_t sb, const float* x, int sc, int m0) {
    int tid = threadIdx.x;
    #pragma unroll
    for (int i = 0; i < 8; i++) {               // 128 rows x 16 16B-chunks
        int idx = tid + i * 256;
        int r = idx >> 4, u = idx & 15;
        cp_async16(sb + STG_OFF + r * 256 + u * 16,
                   x + (size_t)(m0 + r) * DIN + sc * 64 + u * 4);
    }
}

__device__ __forceinline__ void load_B(uint32_t sb, int buf, int sc, int n0) {
    uint32_t base = sb + B_OFF + buf * 65536;
    int tid = threadIdx.x;
    #pragma unroll
    for (int i = 0; i < 8; i++) {               // 256 rows x 8 chunks
        int idx = tid + i * 256;
        int r = idx >> 3, t = idx & 7;
        uint32_t sw = (uint32_t)(r * 128 + ((t ^ (r & 7)) << 4));
        const __nv_bfloat16* brow = d_ws + (size_t)(n0 + r) * KSPLIT + sc * 64 + t * 8;
        cp_async16(base + sw, brow);
        cp_async16(base + 32768 + sw, brow + DIN);
    }
}

// split staging fp32 -> AHI/ALO bf16 (swizzled)
__device__ __forceinline__ void convert_A(char* smem, int buf) {
    int tid = threadIdx.x;
    char* stg = smem + STG_OFF;
    char* ahi = smem + A_OFF + buf * 32768;
    char* alo = ahi + 16384;
    #pragma unroll
    for (int i = 0; i < 4; i++) {               // 128 rows x 8 t-units
        int unit = tid + i * 256;
        int r = unit >> 3, t = unit & 7;
        const float4* s = (const float4*)(stg + r * 256 + t * 32);
        float4 v0 = s[0], v1 = s[1];
        float h0 = __bfloat162float(__float2bfloat16(v0.x));
        float h1 = __bfloat162float(__float2bfloat16(v0.y));
        float h2 = __bfloat162float(__float2bfloat16(v0.z));
        float h3 = __bfloat162float(__float2bfloat16(v0.w));
        float h4 = __bfloat162float(__float2bfloat16(v1.x));
        float h5 = __bfloat162float(__float2bfloat16(v1.y));
        float h6 = __bfloat162float(__float2bfloat16(v1.z));
        float h7 = __bfloat162float(__float2bfloat16(v1.w));
        uint4 hv, lv;
        hv.x = pack_bf16(h0, h1);  hv.y = pack_bf16(h2, h3);
        hv.z = pack_bf16(h4, h5);  hv.w = pack_bf16(h6, h7);
        lv.x = pack_bf16(v0.x - h0, v0.y - h1);
        lv.y = pack_bf16(v0.z - h2, v0.w - h3);
        lv.z = pack_bf16(v1.x - h4, v1.y - h5);
        lv.w = pack_bf16(v1.z - h6, v1.w - h7);
        uint32_t sw = (uint32_t)(r * 128 + ((t ^ (r & 7)) << 4));
        *(uint4*)(ahi + sw) = hv;
        *(uint4*)(alo + sw) = lv;
    }
}

__device__ __forceinline__ void ldmx4(uint32_t& r0, uint32_t& r1, uint32_t& r2,
                                      uint32_t& r3, uint32_t addr) {
    asm volatile("ldmatrix.sync.aligned.m8n8.x4.shared.b16 {%0,%1,%2,%3}, [%4];"
                 : "=r"(r0), "=r"(r1), "=r"(r2), "=r"(r3) : "r"(addr));
}

__device__ __forceinline__ void mma16816(float* c, const uint32_t* a, const uint32_t* b) {
    asm volatile(
        "mma.sync.aligned.m16n8k16.row.col.f32.bf16.bf16.f32 "
        "{%0,%1,%2,%3}, {%4,%5,%6,%7}, {%8,%9}, {%0,%1,%2,%3};"
        : "+f"(c[0]), "+f"(c[1]), "+f"(c[2]), "+f"(c[3])
        : "r"(a[0]), "r"(a[1]), "r"(a[2]), "r"(a[3]), "r"(b[0]), "r"(b[1]));
}

__global__ __launch_bounds__(256) void gemm_mma_kernel(const float* __restrict__ x) {
    extern __shared__ __align__(1024) char smem[];
    uint32_t sb = smem_u32(smem);
    const int tid  = threadIdx.x;
    const int wid  = tid >> 5, lane = tid & 31;
    const int n0 = blockIdx.x * 256;
    const int m0 = blockIdx.y * 128;
    const int wm = (wid & 1) * 64;        // warp M offset
    const int wn = (wid >> 1) * 64;       // warp N offset

    const int q  = lane >> 3;             // ldmatrix matrix index 0..3
    const int rq = lane & 7;
    const int a_rowl   = (q & 1) * 8 + rq;
    const int a_chunkq = q >> 1;
    const int b_rowl   = (q >> 1) * 8 + rq;
    const int b_chunkq = q & 1;

    float acc[4][8][4];
    #pragma unroll
    for (int i = 0; i < 4; i++)
        #pragma unroll
        for (int j = 0; j < 8; j++)
            #pragma unroll
            for (int v = 0; v < 4; v++) acc[i][j][v] = 0.f;

    // prologue: stage 0 loads
    load_A_fp32(sb, x, 0, m0);
    load_B(sb, 0, 0, n0);
    asm volatile("cp.async.commit_group;" ::: "memory");

    for (int sc = 0; sc < NSUPER; ++sc) {
        int buf = sc & 1;
        asm volatile("cp.async.wait_group 0;" ::: "memory");
        __syncthreads();                        // all warps past compute sc-1
        convert_A(smem, buf);
        __syncthreads();                        // staging free, A(buf) visible
        if (sc + 1 < NSUPER) {
            load_A_fp32(sb, x, sc + 1, m0);
            load_B(sb, (sc + 1) & 1, sc + 1, n0);
        }
        asm volatile("cp.async.commit_group;" ::: "memory");

        uint32_t Ahi = sb + A_OFF + buf * 32768;
        uint32_t Alo = Ahi + 16384;
        uint32_t Bhi = sb + B_OFF + buf * 65536;
        uint32_t Blo = Bhi + 32768;

        #pragma unroll
        for (int ks = 0; ks < 4; ++ks) {
            uint32_t ah[4][4], al[4][4];
            uint32_t b[8][2];
            // A-hi frags
            #pragma unroll
            for (int mi = 0; mi < 4; ++mi) {
                int row = wm + mi * 16 + a_rowl;
                uint32_t addr = Ahi + row * 128 +
                                (uint32_t)(((ks * 2 + a_chunkq) ^ (row & 7)) << 4);
                ldmx4(ah[mi][0], ah[mi][1], ah[mi][2], ah[mi][3], addr);
            }
            // B-hi frags
            #pragma unroll
            for (int nj = 0; nj < 4; ++nj) {
                int n = wn + nj * 16 + b_rowl;
                uint32_t addr = Bhi + n * 128 +
                                (uint32_t)(((ks * 2 + b_chunkq) ^ (n & 7)) << 4);
                uint32_t r0, r1, r2, r3;
                ldmx4(r0, r1, r2, r3, addr);
                b[nj * 2 + 0][0] = r0; b[nj * 2 + 0][1] = r1;
                b[nj * 2 + 1][0] = r2; b[nj * 2 + 1][1] = r3;
            }
            #pragma unroll
            for (int mi = 0; mi < 4; ++mi)
                #pragma unroll
                for (int nj = 0; nj < 8; ++nj)
                    mma16816(acc[mi][nj], ah[mi], b[nj]);
            // A-lo ; Al x Bh
            #pragma unroll
            for (int mi = 0; mi < 4; ++mi) {
                int row = wm + mi * 16 + a_rowl;
                uint32_t addr = Alo + row * 128 +
                                (uint32_t)(((ks * 2 + a_chunkq) ^ (row & 7)) << 4);
                ldmx4(al[mi][0], al[mi][1], al[mi][2], al[mi][3], addr);
            }
            #pragma unroll
            for (int mi = 0; mi < 4; ++mi)
                #pragma unroll
                for (int nj = 0; nj < 8; ++nj)
                    mma16816(acc[mi][nj], al[mi], b[nj]);
            // B-lo ; Ah x Bl
            #pragma unroll
            for (int nj = 0; nj < 4; ++nj) {
                int n = wn + nj * 16 + b_rowl;
                uint32_t addr = Blo + n * 128 +
                                (uint32_t)(((ks * 2 + b_chunkq) ^ (n & 7)) << 4);
                uint32_t r0, r1, r2, r3;
                ldmx4(r0, r1, r2, r3, addr);
                b[nj * 2 + 0][0] = r0; b[nj * 2 + 0][1] = r1;
                b[nj * 2 + 1][0] = r2; b[nj * 2 + 1][1] = r3;
            }
            #pragma unroll
            for (int mi = 0; mi < 4; ++mi)
                #pragma unroll
                for (int nj = 0; nj < 8; ++nj)
                    mma16816(acc[mi][nj], ah[mi], b[nj]);
        }
    }

    // epilogue
    const int erow = lane >> 2;
    const int ecol = (lane & 3) * 2;
    #pragma unroll
    for (int mi = 0; mi < 4; ++mi) {
        #pragma unroll
        for (int nj = 0; nj < 8; ++nj) {
            int gr = m0 + wm + mi * 16 + erow;
            int gc = n0 + wn + nj * 8 + ecol;
            float* o0 = &d_h0[(size_t)gr * HH + gc];
            o0[0] = acc[mi][nj][0];
            o0[1] = acc[mi][nj][1];
            float* o1 = &d_h0[(size_t)(gr + 8) * HH + gc];
            o1[0] = acc[mi][nj][2];
            o1[1] = acc[mi][nj][3];
        }
    }
}

// ---------------- fused gather: agg + self + bias + relu + score dots -------
__global__ __launch_bounds__(128) void gather_kernel(
    const float* __restrict__ gcn_b, const float* __restrict__ w1,
    const float* __restrict__ w2,    const float* __restrict__ sag_b) {
    __shared__ float red[8];
    int n = blockIdx.x;
    int tid = threadIdx.x;
    int lane = tid & 31, w = tid >> 5;
    int beg = d_rowptr[n], end = d_rowptr[n + 1];
    float din = d_dinv[n];
    int f = tid * 4;

    float4 hv = *(const float4*)&d_h0[(size_t)n * HH + f];
    float d2 = din * din;
    float4 acc = make_float4(hv.x * d2, hv.y * d2, hv.z * d2, hv.w * d2);

    for (int j = beg; j < end; ++j) {
        int s = d_esrc[j];
        float c = d_dinv[s] * din;
        float4 xv = *(const float4*)&d_h0[(size_t)s * HH + f];
        acc.x += xv.x * c;
        acc.y += xv.y * c;
        acc.z += xv.z * c;
        acc.w += xv.w * c;
    }
    float4 bv = *(const float4*)&gcn_b[f];
    acc.x = fmaxf(acc.x + bv.x, 0.f);
    acc.y = fmaxf(acc.y + bv.y, 0.f);
    acc.z = fmaxf(acc.z + bv.z, 0.f);
    acc.w = fmaxf(acc.w + bv.w, 0.f);
    *(float4*)&d_h[(size_t)n * HH + f] = acc;

    float4 w1v = *(const float4*)&w1[f];
    float4 w2v = *(const float4*)&w2[f];
    float a = acc.x * w1v.x + acc.y * w1v.y + acc.z * w1v.z + acc.w * w1v.w;
    float b = acc.x * w2v.x + acc.y * w2v.y + acc.z * w2v.z + acc.w * w2v.w;
    #pragma unroll
    for (int o = 16; o > 0; o >>= 1) {
        a += __shfl_down_sync(0xffffffffu, a, o);
        b += __shfl_down_sync(0xffffffffu, b, o);
    }
    if (lane == 0) { red[w] = a; red[w + 4] = b; }
    __syncthreads();
    if (tid == 0) {
        d_s[n]  = red[0] + red[1] + red[2] + red[3] + sag_b[0];
        d_s2[n] = red[4] + red[5] + red[6] + red[7];
        d_cnt[n] = 0;      // self-clean for next invocation
    }
}

__global__ void score_edge_kernel(const int* __restrict__ src, const int* __restrict__ dst) {
    int e = blockIdx.x * blockDim.x + threadIdx.x;
    if (e < EE) atomicAdd(&d_s[dst[e]], d_s2[src[e]]);
}

// ---------------- fused topk(250 of 500) + pooled sums ----------------------
__global__ __launch_bounds__(256) void topk_pool_kernel() {
    __shared__ float key[512];
    __shared__ int   kid[512];
    __shared__ float st[KKc];
    int g = blockIdx.x;
    int tid = threadIdx.x;
    for (int i = tid; i < 512; i += 256) {
        if (i < NPGc) { key[i] = d_s[g * NPGc + i]; kid[i] = i; }
        else          { key[i] = -FLT_MAX;          kid[i] = i; }
    }
    for (int k = 2; k <= 512; k <<= 1) {
        for (int j = k >> 1; j > 0; j >>= 1) {
            __syncthreads();
            for (int t = tid; t < 512; t += 256) {
                int p = t ^ j;
                if (p > t) {
                    float ka = key[t], kb = key[p];
                    int   ia = kid[t], ib = kid[p];
                    bool b_gt_a = (kb > ka) || (kb == ka && ib < ia);
                    bool desc = ((t & k) == 0);
                    bool do_swap = desc ? b_gt_a : (!b_gt_a && (ka != kb || ia != ib));
                    if (do_swap) {
                        key[t] = kb; key[p] = ka;
                        kid[t] = ib; kid[p] = ia;
                    }
                }
            }
        }
    }
    __syncthreads();
    if (tid < KKc) st[tid] = tanhf(key[tid]);
    __syncthreads();

    int f1 = tid, f2 = tid + 256;
    float s1 = 0.f, q1 = 0.f, s2 = 0.f, q2 = 0.f;
    for (int k = 0; k < KKc; k++) {
        const float* hr = &d_h[(size_t)(g * NPGc + kid[k]) * HH];
        float t = st[k];
        float v1 = hr[f1] * t;
        float v2 = hr[f2] * t;
        s1 += v1; q1 += v1 * v1;
        s2 += v2; q2 += v2 * v2;
    }
    d_S[g * HH + f1] = s1;
    d_S[g * HH + f2] = s2;
    atomicAdd(&d_ssq[f1], q1);
    atomicAdd(&d_ssq[f2], q2);
}

// ---------------- BN (fused) + mean-pool + FC + log_softmax -----------------
__global__ __launch_bounds__(512) void final_kernel(
    const float* __restrict__ gamma, const float* __restrict__ beta,
    const float* __restrict__ fc_w,  const float* __restrict__ fc_b,
    float* __restrict__ out) {
    __shared__ float mu[HH], rstd[HH], lg[GG * CC];
    int tid = threadIdx.x;
    {
        int f = tid;
        float cs = 0.f;
        for (int g = 0; g < GG; g++) cs += d_S[g * HH + f];
        float m = cs * (1.0f / (GG * KKc));
        float ss = d_ssq[f];
        d_ssq[f] = 0.f;                    // self-clean for next invocation
        float var = ss * (1.0f / (GG * KKc)) - m * m;
        mu[f] = m;
        rstd[f] = rsqrtf(var + EPSc);
    }
    __syncthreads();
    {
        int g = tid >> 2, c = tid & 3;
        float acc = fc_b[c];
        for (int f = 0; f < HH; f++) {
            float pooled = (d_S[g * HH + f] * (1.0f / KKc) - mu[f]) * rstd[f] * gamma[f] + beta[f];
            acc += pooled * fc_w[f * CC + c];
        }
        lg[tid] = acc;
    }
    __syncthreads();
    if (tid < GG) {
        float l0 = lg[tid * 4 + 0], l1 = lg[tid * 4 + 1];
        float l2 = lg[tid * 4 + 2], l3 = lg[tid * 4 + 3];
        float m = fmaxf(fmaxf(l0, l1), fmaxf(l2, l3));
        float lse = m + logf(expf(l0 - m) + expf(l1 - m) + expf(l2 - m) + expf(l3 - m));
        out[tid * 4 + 0] = l0 - lse;
        out[tid * 4 + 1] = l1 - lse;
        out[tid * 4 + 2] = l2 - lse;
        out[tid * 4 + 3] = l3 - lse;
    }
}

// ---------------- launch ----------------
extern "C" void kernel_launch(void* const* d_in, const int* in_sizes, int n_in,
                              void* d_out, int out_size) {
    const float* x      = (const float*)d_in[0];
    const float* gcn_w  = (const float*)d_in[1];
    const float* gcn_b  = (const float*)d_in[2];
    const float* sag_w1 = (const float*)d_in[3];
    const float* sag_w2 = (const float*)d_in[4];
    const float* sag_b  = (const float*)d_in[5];
    const float* bn_g   = (const float*)d_in[6];
    const float* bn_b   = (const float*)d_in[7];
    const float* fc_w   = (const float*)d_in[8];
    const float* fc_b   = (const float*)d_in[9];
    const int*   ei     = (const int*)d_in[10];
    const int* src = ei;
    const int* dst = ei + EE;
    float* out = (float*)d_out;

    cudaFuncSetAttribute(gemm_mma_kernel, cudaFuncAttributeMaxDynamicSharedMemorySize,
                         SMEM_TOTAL_GEMM);

    // gemm kept as 4th launch (ncu capture lands there)
    convert_w_kernel<<<(DIN * HH) / 256, 256>>>(gcn_w);
    csr_count_kernel<<<(EE + 255) / 256, 256>>>(dst);
    csr_scan_kernel<<<1, 1024>>>();
    gemm_mma_kernel<<<dim3(HH / 256, NN / 128), 256, SMEM_TOTAL_GEMM>>>(x);
    csr_fill_kernel<<<(EE + 255) / 256, 256>>>(src, dst);
    gather_kernel<<<NN, 128>>>(gcn_b, sag_w1, sag_w2, sag_b);
    score_edge_kernel<<<(EE + 255) / 256, 256>>>(src, dst);
    topk_pool_kernel<<<GG, 256>>>();
    final_kernel<<<1, 512>>>(bn_g, bn_b, fc_w, fc_b, out);
}